// round 13
// baseline (speedup 1.0000x reference)
#include <cuda_runtime.h>

#define GG    49
#define CQ    64
#define NEGV  (-1e20f)

// RAW logits: [n][49][16]; H slots 0..6 (slot7=NEG), W slots 8..14 (slot15=NEG).
// Diag of H pre-masked to NEG. Softmax is applied by the consumer kernel.
__device__ float g_p[512 * GG * 16];

// ---------------------------------------------------------------------------
// Kernel A: one (n, pass) per block. grid (N, 2), block 128.
// Static smem 28224 B -> 8 blocks/SM -> 1024 blocks in ONE wave.
// pass 0: H logits (diag-masked) -> slots 0..7; pass 1: W logits -> slots 8..15.
// k staged transposed [g*7+j][c]; dots = 32 x LDS.128 + 64 FMA (2 accums).
// ---------------------------------------------------------------------------
__global__ __launch_bounds__(128, 8) void ax_logits(
    const float* __restrict__ qH, const float* __restrict__ kH,
    const float* __restrict__ qW, const float* __restrict__ kW)
{
    __shared__ float smA[7056];
    float* sQ = smA;          // 49 * 68
    float* sK = smA + 3332;   // transposed [g*7+j][c], 49 * 68
    float* sL = smA + 6664;   // 49 * 8

    const int n    = blockIdx.x;
    const int pass = blockIdx.y;
    const int tid  = threadIdx.x;

    const float4* qg = (const float4*)((pass ? qW : qH) + (size_t)n * 3136);
    const float4* kg = (const float4*)((pass ? kW : kH) + (size_t)n * 3136);

    #define STAGE1(i4, qv, kv) {                                    \
        int g = (i4) >> 4, c4 = (i4) & 15;                          \
        ((float4*)(sQ + g * 68))[c4] = (qv);                        \
        int w = (i4) / 112, r4 = (i4) - w * 112, r = 4 * r4;        \
        int cc = r / 7, jj = r - 7 * cc;                            \
        float av[4] = {(kv).x, (kv).y, (kv).z, (kv).w};             \
        _Pragma("unroll")                                           \
        for (int e = 0; e < 4; e++) {                               \
            sK[(w * 7 + jj) * 68 + cc] = av[e];                     \
            if (++jj == 7) { jj = 0; cc++; }                        \
        }                                                           \
    }

    {   // batch 1: 6 LDG.128 in flight
        float4 q0 = qg[tid], q1 = qg[tid + 128], q2 = qg[tid + 256];
        float4 k0 = kg[tid], k1 = kg[tid + 128], k2 = kg[tid + 256];
        STAGE1(tid,       q0, k0);
        STAGE1(tid + 128, q1, k1);
        STAGE1(tid + 256, q2, k2);
    }
    {   // batch 2 (+ tail)
        float4 q0 = qg[tid + 384], q1 = qg[tid + 512], q2 = qg[tid + 640];
        float4 k0 = kg[tid + 384], k1 = kg[tid + 512], k2 = kg[tid + 640];
        float4 q3, k3;
        if (tid < 16) { q3 = qg[tid + 768]; k3 = kg[tid + 768]; }
        STAGE1(tid + 384, q0, k0);
        STAGE1(tid + 512, q1, k1);
        STAGE1(tid + 640, q2, k2);
        if (tid < 16) STAGE1(tid + 768, q3, k3);
    }
    #undef STAGE1
    __syncthreads();

    // 343 dots over 128 threads
    #pragma unroll
    for (int u = 0; u < 3; u++) {
        int idx = tid + u * 128;
        if (idx < 343) {
            const int a0 = idx / 49;
            const int r  = idx - a0 * 49;
            const int a1 = r / 7;
            const int a2 = r - a1 * 7;
            const float4* q = (const float4*)(sQ + (a0 * 7 + a1) * 68);
            const float4* k = (const float4*)(sK + (a0 * 7 + a2) * 68);
            float s0 = 0.f, s1 = 0.f;
            #pragma unroll
            for (int c4 = 0; c4 < 16; c4 += 2) {
                float4 qa = q[c4],     ka = k[c4];
                float4 qb = q[c4 + 1], kb = k[c4 + 1];
                s0 = fmaf(qa.x, ka.x, s0); s0 = fmaf(qa.y, ka.y, s0);
                s0 = fmaf(qa.z, ka.z, s0); s0 = fmaf(qa.w, ka.w, s0);
                s1 = fmaf(qb.x, kb.x, s1); s1 = fmaf(qb.y, kb.y, s1);
                s1 = fmaf(qb.z, kb.z, s1); s1 = fmaf(qb.w, kb.w, s1);
            }
            float v = s0 + s1;
            int pos;
            if (pass == 0) { pos = a1 * 7 + a0; if (a1 == a2) v = NEGV; }
            else           { pos = a0 * 7 + a1; }
            sL[pos * 8 + a2] = v;
        }
    }
    __syncthreads();

    // write raw logits half-row (2 x STG.128)
    if (tid < GG) {
        const float* row = sL + tid * 8;
        float4* dst = (float4*)&g_p[(size_t)n * 784 + tid * 16 + pass * 8];
        dst[0] = make_float4(row[0], row[1], row[2], row[3]);
        dst[1] = make_float4(row[4], row[5], row[6], NEGV);
    }
}

// ---------------------------------------------------------------------------
// Kernel B: out[n,c,h,w] = sum_j p[pos][j]*vH[n,w,c,j] + sum_y p[pos][8+y]*vW[n,h,c,y]
// grid = (N, Cv/128), block = 128. Dyn smem 53312 B -> 4 blocks/SM.
// WARP-PRIVATE coalesced V staging: each warp stages its own 32 channels via
// 12.25 x LDG.128 (7x fewer L1 wavefronts than scalar stride-7 LDG), consumes
// with __syncwarp only. Softmax of raw logits done in-block (tid<49).
// sOut aliases sVH: each warp's output rows land exactly in its own slice.
// ---------------------------------------------------------------------------
__global__ __launch_bounds__(128, 4) void ax_attn_out(
    const float* __restrict__ vH, const float* __restrict__ vW,
    float* __restrict__ out, int Cv)
{
    extern __shared__ float smB[];
    float* sVH = smB;            // 4 warp slices x 1568 = 6272 (aliased as sOut)
    float* sVW = smB + 6272;     // 6272
    float* sP  = smB + 12544;    // 784

    const int n    = blockIdx.x;
    const int c0   = blockIdx.y * 128;
    const int tid  = threadIdx.x;
    const int lane = tid & 31;
    const int wid  = tid >> 5;

    // ---- stage p (raw logits) ----
    {
        const float4* pg = (const float4*)&g_p[(size_t)n * 784];
        float4 p0 = pg[tid];
        float4 p1; bool hp = (tid < 68);
        if (hp) p1 = pg[128 + tid];
        ((float4*)sP)[tid] = p0;
        if (hp) ((float4*)sP)[128 + tid] = p1;
    }

    // ---- warp-private vH staging: slice = 32 channels x 7g x 7j ----
    const float4* vH4 = (const float4*)vH;
    const float4* vW4 = (const float4*)vW;
    const size_t gbase = (size_t)(n * 7) * 896 + (size_t)(c0 + 32 * wid) * 7 / 4;
    float4* slH = (float4*)(sVH + wid * 1568);
    float4* slW = (float4*)(sVW + wid * 1568);

    {
        float4 b[6];
        #pragma unroll
        for (int u = 0; u < 6; u++) {
            int i4 = u * 32 + lane, g = i4 / 56;
            b[u] = vH4[gbase + i4 + 840 * g];
        }
        #pragma unroll
        for (int u = 0; u < 6; u++) slH[u * 32 + lane] = b[u];
    }
    {
        float4 b[6], t;
        #pragma unroll
        for (int u = 6; u < 12; u++) {
            int i4 = u * 32 + lane, g = i4 / 56;
            b[u - 6] = vH4[gbase + i4 + 840 * g];
        }
        if (lane < 8) t = vH4[gbase + (384 + lane) + 840 * 6];
        #pragma unroll
        for (int u = 6; u < 12; u++) slH[u * 32 + lane] = b[u - 6];
        if (lane < 8) slH[384 + lane] = t;
    }
    __syncthreads();   // sP staged (and vH stores globally visible)

    // ---- cache own slice's vH (stride 7, conflict-free) ----
    float vh[49];
    const float* mySlH = sVH + wid * 1568 + lane * 7;
    #pragma unroll
    for (int w = 0; w < 7; w++)
        #pragma unroll
        for (int j = 0; j < 7; j++)
            vh[w * 7 + j] = mySlH[w * 224 + j];
    __syncwarp();      // own slice consumed -> this warp may overwrite it (sOut)

    // ---- warp-private vW staging (separate buffer, independent of softmax) ----
    {
        float4 b[6];
        #pragma unroll
        for (int u = 0; u < 6; u++) {
            int i4 = u * 32 + lane, g = i4 / 56;
            b[u] = vW4[gbase + i4 + 840 * g];
        }
        #pragma unroll
        for (int u = 0; u < 6; u++) slW[u * 32 + lane] = b[u];
    }
    {
        float4 b[6], t;
        #pragma unroll
        for (int u = 6; u < 12; u++) {
            int i4 = u * 32 + lane, g = i4 / 56;
            b[u - 6] = vW4[gbase + i4 + 840 * g];
        }
        if (lane < 8) t = vW4[gbase + (384 + lane) + 840 * 6];
        #pragma unroll
        for (int u = 6; u < 12; u++) slW[u * 32 + lane] = b[u - 6];
        if (lane < 8) slW[384 + lane] = t;
    }

    // ---- in-block softmax over 16 slots (pads are NEGV -> weight 0) ----
    if (tid < GG) {
        float4* rowv = (float4*)(sP + tid * 16);
        float4 r0 = rowv[0], r1 = rowv[1], r2 = rowv[2], r3 = rowv[3];
        float m = r0.x;
        m = fmaxf(m, r0.y); m = fmaxf(m, r0.z); m = fmaxf(m, r0.w);
        m = fmaxf(m, r1.x); m = fmaxf(m, r1.y); m = fmaxf(m, r1.z);
        m = fmaxf(m, r2.x); m = fmaxf(m, r2.y); m = fmaxf(m, r2.z); m = fmaxf(m, r2.w);
        m = fmaxf(m, r3.x); m = fmaxf(m, r3.y); m = fmaxf(m, r3.z);
        r0.x = __expf(r0.x - m); r0.y = __expf(r0.y - m);
        r0.z = __expf(r0.z - m); r0.w = __expf(r0.w - m);
        r1.x = __expf(r1.x - m); r1.y = __expf(r1.y - m);
        r1.z = __expf(r1.z - m); r1.w = 0.f;
        r2.x = __expf(r2.x - m); r2.y = __expf(r2.y - m);
        r2.z = __expf(r2.z - m); r2.w = __expf(r2.w - m);
        r3.x = __expf(r3.x - m); r3.y = __expf(r3.y - m);
        r3.z = __expf(r3.z - m); r3.w = 0.f;
        float sum = r0.x + r0.y + r0.z + r0.w + r1.x + r1.y + r1.z
                  + r2.x + r2.y + r2.z + r2.w + r3.x + r3.y + r3.z;
        float inv = 1.f / sum;
        r0.x *= inv; r0.y *= inv; r0.z *= inv; r0.w *= inv;
        r1.x *= inv; r1.y *= inv; r1.z *= inv;
        r2.x *= inv; r2.y *= inv; r2.z *= inv; r2.w *= inv;
        r3.x *= inv; r3.y *= inv; r3.z *= inv;
        rowv[0] = r0; rowv[1] = r1; rowv[2] = r2; rowv[3] = r3;
    }
    __syncthreads();   // softmax done; vW stores (warp-local) also fenced

    // ---- compute: 49 outputs per thread, stored into own sOut slice ----
    float* sOut = sVH;
    const float* mySlW = sVW + wid * 1568 + lane * 7;
    #pragma unroll
    for (int h = 0; h < 7; h++) {
        float vw0 = mySlW[h * 224 + 0];
        float vw1 = mySlW[h * 224 + 1];
        float vw2 = mySlW[h * 224 + 2];
        float vw3 = mySlW[h * 224 + 3];
        float vw4 = mySlW[h * 224 + 4];
        float vw5 = mySlW[h * 224 + 5];
        float vw6 = mySlW[h * 224 + 6];
        #pragma unroll
        for (int w = 0; w < 7; w++) {
            const float4* p4 = (const float4*)(sP + (h * 7 + w) * 16);
            float4 a = p4[0], b = p4[1], c4 = p4[2], d4 = p4[3];
            float s = a.x * vh[w * 7 + 0];
            s = fmaf(a.y, vh[w * 7 + 1], s);
            s = fmaf(a.z, vh[w * 7 + 2], s);
            s = fmaf(a.w, vh[w * 7 + 3], s);
            s = fmaf(b.x, vh[w * 7 + 4], s);
            s = fmaf(b.y, vh[w * 7 + 5], s);
            s = fmaf(b.z, vh[w * 7 + 6], s);
            s = fmaf(c4.x, vw0, s);
            s = fmaf(c4.y, vw1, s);
            s = fmaf(c4.z, vw2, s);
            s = fmaf(c4.w, vw3, s);
            s = fmaf(d4.x, vw4, s);
            s = fmaf(d4.y, vw5, s);
            s = fmaf(d4.z, vw6, s);
            sOut[tid * 49 + h * 7 + w] = s;   // stays inside this warp's slice
        }
    }
    __syncthreads();

    // ---- coalesced float4 writeout ----
    float* dst = out + ((size_t)n * Cv + c0) * GG;
    #pragma unroll
    for (int u = 0; u < 12; u++)
        ((float4*)dst)[tid + u * 128] = ((const float4*)sOut)[tid + u * 128];
    if (tid < 32)
        ((float4*)dst)[1536 + tid] = ((const float4*)sOut)[1536 + tid];
}

// ---------------------------------------------------------------------------
extern "C" void kernel_launch(void* const* d_in, const int* in_sizes, int n_in,
                              void* d_out, int out_size)
{
    const float* qH = (const float*)d_in[0];
    const float* kH = (const float*)d_in[1];
    const float* vH = (const float*)d_in[2];
    const float* qW = (const float*)d_in[3];
    const float* kW = (const float*)d_in[4];
    const float* vW = (const float*)d_in[5];

    const int B  = in_sizes[0] / (7 * CQ);    // 3584
    const int N  = B / 7;                     // 512
    const int Cv = in_sizes[2] / (B * 7);     // 512

    const size_t smemB = (size_t)13328 * sizeof(float);  // 53312
    cudaFuncSetAttribute(ax_attn_out, cudaFuncAttributeMaxDynamicSharedMemorySize, (int)smemB);

    ax_logits<<<dim3(N, 2), 128>>>(qH, kH, qW, kW);
    ax_attn_out<<<dim3(N, Cv / 128), 128, smemB>>>(vH, vW, (float*)d_out, Cv);
}

// round 14
// speedup vs baseline: 1.5465x; 1.5465x over previous
#include <cuda_runtime.h>

#define GG    49
#define CQ    64
#define NEGV  (-1e20f)

// Softmax probabilities: [n][49][16]; pH slots 0..6 (7=0), pW slots 8..14 (15=0).
__device__ float g_p[512 * GG * 16];

// ---------------------------------------------------------------------------
// Kernel A (R11-proven): logits (H diag-masked + W) + softmax over 14, per n.
// grid = N, block = 256, launch_bounds(256,4) -> 4 blocks/SM (smem 56.4KB).
// ---------------------------------------------------------------------------
__global__ __launch_bounds__(256, 4) void ax_attn_logits(
    const float* __restrict__ qH, const float* __restrict__ kH,
    const float* __restrict__ qW, const float* __restrict__ kW)
{
    extern __shared__ float smA[];
    float* sQH = smA;              // 49 * 68
    float* sKH = smA + 3332;       // transposed [w*7+j][c], 49 * 68
    float* sQW = smA + 6664;
    float* sKW = smA + 9996;
    float* sL  = smA + 13328;      // 49 * 16

    const int n   = blockIdx.x;
    const int tid = threadIdx.x;

    const float4* q1 = (const float4*)(qH + (size_t)n * 3136);
    const float4* q2 = (const float4*)(qW + (size_t)n * 3136);
    const float4* k1 = (const float4*)(kH + (size_t)n * 3136);
    const float4* k2 = (const float4*)(kW + (size_t)n * 3136);

    #define SCATTER_K(i4, vk1, vk2)                                   \
    {                                                                 \
        int w = (i4) / 112, r4 = (i4) - w * 112, r = 4 * r4;          \
        int c = r / 7, j = r - 7 * c;                                 \
        float av[4] = {(vk1).x, (vk1).y, (vk1).z, (vk1).w};           \
        float bv[4] = {(vk2).x, (vk2).y, (vk2).z, (vk2).w};           \
        _Pragma("unroll")                                             \
        for (int e = 0; e < 4; e++) {                                 \
            sKH[(w * 7 + j) * 68 + c] = av[e];                        \
            sKW[(w * 7 + j) * 68 + c] = bv[e];                        \
            if (++j == 7) { j = 0; c++; }                             \
        }                                                             \
    }
    #define STORE_Q(i4, vq1, vq2)                                     \
    {                                                                 \
        int g = (i4) >> 4, c4 = (i4) & 15;                            \
        ((float4*)(sQH + g * 68))[c4] = (vq1);                        \
        ((float4*)(sQW + g * 68))[c4] = (vq2);                        \
    }

    {
        int ia = tid, ib = tid + 256;
        float4 aq1 = q1[ia], aq2 = q2[ia], ak1 = k1[ia], ak2 = k2[ia];
        float4 bq1 = q1[ib], bq2 = q2[ib], bk1 = k1[ib], bk2 = k2[ib];
        STORE_Q(ia, aq1, aq2); SCATTER_K(ia, ak1, ak2);
        STORE_Q(ib, bq1, bq2); SCATTER_K(ib, bk1, bk2);
    }
    {
        int ic = tid + 512;
        float4 cq1 = q1[ic], cq2 = q2[ic], ck1 = k1[ic], ck2 = k2[ic];
        if (tid < 16) {
            int id = tid + 768;
            float4 dq1 = q1[id], dq2 = q2[id], dk1 = k1[id], dk2 = k2[id];
            STORE_Q(ic, cq1, cq2); SCATTER_K(ic, ck1, ck2);
            STORE_Q(id, dq1, dq2); SCATTER_K(id, dk1, dk2);
        } else {
            STORE_Q(ic, cq1, cq2); SCATTER_K(ic, ck1, ck2);
        }
    }
    #undef SCATTER_K
    #undef STORE_Q
    __syncthreads();

    #pragma unroll
    for (int u = 0; u < 2; u++) {
        int idx = tid + u * 256;
        if (idx < 343) {
            const int a0 = idx / 49;
            const int r  = idx - a0 * 49;
            const int a1 = r / 7;
            const int a2 = r - a1 * 7;

            {
                const float4* q = (const float4*)(sQH + (a0 * 7 + a1) * 68);
                const float4* k = (const float4*)(sKH + (a0 * 7 + a2) * 68);
                float s0 = 0.f, s1 = 0.f;
                #pragma unroll
                for (int c4 = 0; c4 < 16; c4 += 2) {
                    float4 qa = q[c4],     ka = k[c4];
                    float4 qb = q[c4 + 1], kb = k[c4 + 1];
                    s0 = fmaf(qa.x, ka.x, s0); s0 = fmaf(qa.y, ka.y, s0);
                    s0 = fmaf(qa.z, ka.z, s0); s0 = fmaf(qa.w, ka.w, s0);
                    s1 = fmaf(qb.x, kb.x, s1); s1 = fmaf(qb.y, kb.y, s1);
                    s1 = fmaf(qb.z, kb.z, s1); s1 = fmaf(qb.w, kb.w, s1);
                }
                sL[(a1 * 7 + a0) * 16 + a2] = (a1 == a2) ? NEGV : (s0 + s1);
            }
            {
                const float4* q = (const float4*)(sQW + (a0 * 7 + a1) * 68);
                const float4* k = (const float4*)(sKW + (a0 * 7 + a2) * 68);
                float s0 = 0.f, s1 = 0.f;
                #pragma unroll
                for (int c4 = 0; c4 < 16; c4 += 2) {
                    float4 qa = q[c4],     ka = k[c4];
                    float4 qb = q[c4 + 1], kb = k[c4 + 1];
                    s0 = fmaf(qa.x, ka.x, s0); s0 = fmaf(qa.y, ka.y, s0);
                    s0 = fmaf(qa.z, ka.z, s0); s0 = fmaf(qa.w, ka.w, s0);
                    s1 = fmaf(qb.x, kb.x, s1); s1 = fmaf(qb.y, kb.y, s1);
                    s1 = fmaf(qb.z, kb.z, s1); s1 = fmaf(qb.w, kb.w, s1);
                }
                sL[(a0 * 7 + a1) * 16 + 8 + a2] = s0 + s1;
            }
        }
    }
    __syncthreads();

    if (tid < GG) {
        const float* row = sL + tid * 16;
        float m = row[0];
        #pragma unroll
        for (int i = 1; i < 7; i++)  m = fmaxf(m, row[i]);
        #pragma unroll
        for (int i = 8; i < 15; i++) m = fmaxf(m, row[i]);
        float e[16], sum = 0.f;
        #pragma unroll
        for (int i = 0; i < 7; i++)  { e[i] = __expf(row[i] - m); sum += e[i]; }
        #pragma unroll
        for (int i = 8; i < 15; i++) { e[i] = __expf(row[i] - m); sum += e[i]; }
        float inv = 1.f / sum;
        float4* dst = (float4*)&g_p[((size_t)n * GG + tid) * 16];
        dst[0] = make_float4(e[0] * inv,  e[1] * inv,  e[2] * inv,  e[3] * inv);
        dst[1] = make_float4(e[4] * inv,  e[5] * inv,  e[6] * inv,  0.f);
        dst[2] = make_float4(e[8] * inv,  e[9] * inv,  e[10] * inv, e[11] * inv);
        dst[3] = make_float4(e[12] * inv, e[13] * inv, e[14] * inv, 0.f);
    }
}

// ---------------------------------------------------------------------------
// Kernel B: out[n,c,h,w] = sum_j p[pos][j]*vH[n,w,c,j] + sum_y p[pos][8+y]*vW[n,h,c,y]
// grid = (N, Cv/128), block = 128, dyn smem 53312 -> 4 blocks/SM.
// Warp-private coalesced V staging (LDG.128 -> STS.128, 4 wf each, vs 7 wf per
// scalar stride-28B LDG). launch_bounds(128,5) caps regs at 102 (no spill:
// staging transients are dead before vh[49] goes live; softmax NOT in-block).
// Slice reuse guarded by __syncwarp only; block barriers only for sP/writeout.
// ---------------------------------------------------------------------------
__global__ __launch_bounds__(128, 5) void ax_attn_out(
    const float* __restrict__ vH, const float* __restrict__ vW,
    float* __restrict__ out, int Cv)
{
    extern __shared__ float smB[];
    float* sVH = smB;            // 4 warp slices x 1568 = 6272 (aliased as sOut)
    float* sVW = smB + 6272;     // 6272
    float* sP  = smB + 12544;    // 784

    const int n    = blockIdx.x;
    const int c0   = blockIdx.y * 128;
    const int tid  = threadIdx.x;
    const int lane = tid & 31;
    const int wid  = tid >> 5;

    // ---- stage p (probabilities) ----
    {
        const float4* pg = (const float4*)&g_p[(size_t)n * 784];
        float4 p0 = pg[tid];
        float4 p1; bool hp = (tid < 68);
        if (hp) p1 = pg[128 + tid];
        ((float4*)sP)[tid] = p0;
        if (hp) ((float4*)sP)[128 + tid] = p1;
    }

    // ---- warp-private coalesced V staging ----
    // warp slice: channels [c0+32*wid, +32), per g a contiguous 224-float run.
    const int rs4 = Cv * 7 / 4;                       // 896: per-g stride in float4
    const size_t cb4 = ((size_t)(n * 7) * Cv + (c0 + 32 * wid)) * 7 / 4;
    const float4* gH = (const float4*)vH + cb4;
    const float4* gW = (const float4*)vW + cb4;
    float4* slH = (float4*)(sVH + wid * 1568);
    float4* slW = (float4*)(sVW + wid * 1568);

    #pragma unroll
    for (int rr = 0; rr < 3; rr++) {                  // 3 macro-rounds x 8 LDG.128
        float4 bh[4], bw[4];
        #pragma unroll
        for (int u = 0; u < 4; u++) {
            int i4 = (rr * 4 + u) * 32 + lane;        // 0..383
            int g = i4 / 56;
            bh[u] = gH[i4 + (rs4 - 56) * g];
            bw[u] = gW[i4 + (rs4 - 56) * g];
        }
        #pragma unroll
        for (int u = 0; u < 4; u++) {
            int i4 = (rr * 4 + u) * 32 + lane;
            slH[i4] = bh[u];
            slW[i4] = bw[u];
        }
    }
    if (lane < 8) {                                   // tail i4 = 384..391 (g=6)
        int i4 = 384 + lane;
        float4 th = gH[i4 + (rs4 - 56) * 6];
        float4 tw = gW[i4 + (rs4 - 56) * 6];
        slH[i4] = th;
        slW[i4] = tw;
    }
    __syncthreads();   // sP visible to all; V slices done

    // ---- cache own slice's vH (lane stride 7 -> conflict-free) ----
    float vh[49];
    const float* mySlH = sVH + wid * 1568 + lane * 7;
    #pragma unroll
    for (int w = 0; w < 7; w++)
        #pragma unroll
        for (int j = 0; j < 7; j++)
            vh[w * 7 + j] = mySlH[w * 224 + j];
    __syncwarp();      // own slice consumed -> this warp may overwrite (sOut)

    // ---- compute: 49 outputs, stored into own sOut slice ----
    float* sOut = sVH;
    const float* mySlW = sVW + wid * 1568 + lane * 7;
    #pragma unroll
    for (int h = 0; h < 7; h++) {
        float vw0 = mySlW[h * 224 + 0];
        float vw1 = mySlW[h * 224 + 1];
        float vw2 = mySlW[h * 224 + 2];
        float vw3 = mySlW[h * 224 + 3];
        float vw4 = mySlW[h * 224 + 4];
        float vw5 = mySlW[h * 224 + 5];
        float vw6 = mySlW[h * 224 + 6];
        #pragma unroll
        for (int w = 0; w < 7; w++) {
            const float4* p4 = (const float4*)(sP + (h * 7 + w) * 16);
            float4 a = p4[0], b = p4[1], c4 = p4[2], d4 = p4[3];
            float s = a.x * vh[w * 7 + 0];
            s = fmaf(a.y, vh[w * 7 + 1], s);
            s = fmaf(a.z, vh[w * 7 + 2], s);
            s = fmaf(a.w, vh[w * 7 + 3], s);
            s = fmaf(b.x, vh[w * 7 + 4], s);
            s = fmaf(b.y, vh[w * 7 + 5], s);
            s = fmaf(b.z, vh[w * 7 + 6], s);
            s = fmaf(c4.x, vw0, s);
            s = fmaf(c4.y, vw1, s);
            s = fmaf(c4.z, vw2, s);
            s = fmaf(c4.w, vw3, s);
            s = fmaf(d4.x, vw4, s);
            s = fmaf(d4.y, vw5, s);
            s = fmaf(d4.z, vw6, s);
            sOut[tid * 49 + h * 7 + w] = s;   // inside own warp slice
        }
    }
    __syncthreads();

    // ---- coalesced float4 writeout ----
    float* dst = out + ((size_t)n * Cv + c0) * GG;
    #pragma unroll
    for (int u = 0; u < 12; u++)
        ((float4*)dst)[tid + u * 128] = ((const float4*)sOut)[tid + u * 128];
    if (tid < 32)
        ((float4*)dst)[1536 + tid] = ((const float4*)sOut)[1536 + tid];
}

// ---------------------------------------------------------------------------
extern "C" void kernel_launch(void* const* d_in, const int* in_sizes, int n_in,
                              void* d_out, int out_size)
{
    const float* qH = (const float*)d_in[0];
    const float* kH = (const float*)d_in[1];
    const float* vH = (const float*)d_in[2];
    const float* qW = (const float*)d_in[3];
    const float* kW = (const float*)d_in[4];
    const float* vW = (const float*)d_in[5];

    const int B  = in_sizes[0] / (7 * CQ);    // 3584
    const int N  = B / 7;                     // 512
    const int Cv = in_sizes[2] / (B * 7);     // 512

    const size_t smemA = (size_t)14112 * sizeof(float);  // 56448
    const size_t smemB = (size_t)13328 * sizeof(float);  // 53312
    cudaFuncSetAttribute(ax_attn_logits, cudaFuncAttributeMaxDynamicSharedMemorySize, (int)smemA);
    cudaFuncSetAttribute(ax_attn_out,    cudaFuncAttributeMaxDynamicSharedMemorySize, (int)smemB);

    ax_attn_logits<<<N, 256, smemA>>>(qH, kH, qW, kW);
    ax_attn_out<<<dim3(N, Cv / 128), 128, smemB>>>(vH, vW, (float*)d_out, Cv);
}

// round 15
// speedup vs baseline: 1.7937x; 1.1599x over previous
#include <cuda_runtime.h>

#define GG    49
#define CQ    64
#define NEGV  (-1e20f)

// Softmax probabilities: [n][49][16]; pH slots 0..6 (7=0), pW slots 8..14 (15=0).
__device__ float g_p[512 * GG * 16];

// ---------------------------------------------------------------------------
// Kernel A (R11-proven): logits (H diag-masked + W) + softmax over 14, per n.
// grid = N, block = 256, launch_bounds(256,4) -> 4 blocks/SM (smem 56.4KB).
// Ends with griddepcontrol.launch_dependents so PDL-dependent B starts early.
// ---------------------------------------------------------------------------
__global__ __launch_bounds__(256, 4) void ax_attn_logits(
    const float* __restrict__ qH, const float* __restrict__ kH,
    const float* __restrict__ qW, const float* __restrict__ kW)
{
    extern __shared__ float smA[];
    float* sQH = smA;              // 49 * 68
    float* sKH = smA + 3332;       // transposed [w*7+j][c], 49 * 68
    float* sQW = smA + 6664;
    float* sKW = smA + 9996;
    float* sL  = smA + 13328;      // 49 * 16

    const int n   = blockIdx.x;
    const int tid = threadIdx.x;

    const float4* q1 = (const float4*)(qH + (size_t)n * 3136);
    const float4* q2 = (const float4*)(qW + (size_t)n * 3136);
    const float4* k1 = (const float4*)(kH + (size_t)n * 3136);
    const float4* k2 = (const float4*)(kW + (size_t)n * 3136);

    #define SCATTER_K(i4, vk1, vk2)                                   \
    {                                                                 \
        int w = (i4) / 112, r4 = (i4) - w * 112, r = 4 * r4;          \
        int c = r / 7, j = r - 7 * c;                                 \
        float av[4] = {(vk1).x, (vk1).y, (vk1).z, (vk1).w};           \
        float bv[4] = {(vk2).x, (vk2).y, (vk2).z, (vk2).w};           \
        _Pragma("unroll")                                             \
        for (int e = 0; e < 4; e++) {                                 \
            sKH[(w * 7 + j) * 68 + c] = av[e];                        \
            sKW[(w * 7 + j) * 68 + c] = bv[e];                        \
            if (++j == 7) { j = 0; c++; }                             \
        }                                                             \
    }
    #define STORE_Q(i4, vq1, vq2)                                     \
    {                                                                 \
        int g = (i4) >> 4, c4 = (i4) & 15;                            \
        ((float4*)(sQH + g * 68))[c4] = (vq1);                        \
        ((float4*)(sQW + g * 68))[c4] = (vq2);                        \
    }

    {
        int ia = tid, ib = tid + 256;
        float4 aq1 = q1[ia], aq2 = q2[ia], ak1 = k1[ia], ak2 = k2[ia];
        float4 bq1 = q1[ib], bq2 = q2[ib], bk1 = k1[ib], bk2 = k2[ib];
        STORE_Q(ia, aq1, aq2); SCATTER_K(ia, ak1, ak2);
        STORE_Q(ib, bq1, bq2); SCATTER_K(ib, bk1, bk2);
    }
    {
        int ic = tid + 512;
        float4 cq1 = q1[ic], cq2 = q2[ic], ck1 = k1[ic], ck2 = k2[ic];
        if (tid < 16) {
            int id = tid + 768;
            float4 dq1 = q1[id], dq2 = q2[id], dk1 = k1[id], dk2 = k2[id];
            STORE_Q(ic, cq1, cq2); SCATTER_K(ic, ck1, ck2);
            STORE_Q(id, dq1, dq2); SCATTER_K(id, dk1, dk2);
        } else {
            STORE_Q(ic, cq1, cq2); SCATTER_K(ic, ck1, ck2);
        }
    }
    #undef SCATTER_K
    #undef STORE_Q
    __syncthreads();

    #pragma unroll
    for (int u = 0; u < 2; u++) {
        int idx = tid + u * 256;
        if (idx < 343) {
            const int a0 = idx / 49;
            const int r  = idx - a0 * 49;
            const int a1 = r / 7;
            const int a2 = r - a1 * 7;

            {
                const float4* q = (const float4*)(sQH + (a0 * 7 + a1) * 68);
                const float4* k = (const float4*)(sKH + (a0 * 7 + a2) * 68);
                float s0 = 0.f, s1 = 0.f;
                #pragma unroll
                for (int c4 = 0; c4 < 16; c4 += 2) {
                    float4 qa = q[c4],     ka = k[c4];
                    float4 qb = q[c4 + 1], kb = k[c4 + 1];
                    s0 = fmaf(qa.x, ka.x, s0); s0 = fmaf(qa.y, ka.y, s0);
                    s0 = fmaf(qa.z, ka.z, s0); s0 = fmaf(qa.w, ka.w, s0);
                    s1 = fmaf(qb.x, kb.x, s1); s1 = fmaf(qb.y, kb.y, s1);
                    s1 = fmaf(qb.z, kb.z, s1); s1 = fmaf(qb.w, kb.w, s1);
                }
                sL[(a1 * 7 + a0) * 16 + a2] = (a1 == a2) ? NEGV : (s0 + s1);
            }
            {
                const float4* q = (const float4*)(sQW + (a0 * 7 + a1) * 68);
                const float4* k = (const float4*)(sKW + (a0 * 7 + a2) * 68);
                float s0 = 0.f, s1 = 0.f;
                #pragma unroll
                for (int c4 = 0; c4 < 16; c4 += 2) {
                    float4 qa = q[c4],     ka = k[c4];
                    float4 qb = q[c4 + 1], kb = k[c4 + 1];
                    s0 = fmaf(qa.x, ka.x, s0); s0 = fmaf(qa.y, ka.y, s0);
                    s0 = fmaf(qa.z, ka.z, s0); s0 = fmaf(qa.w, ka.w, s0);
                    s1 = fmaf(qb.x, kb.x, s1); s1 = fmaf(qb.y, kb.y, s1);
                    s1 = fmaf(qb.z, kb.z, s1); s1 = fmaf(qb.w, kb.w, s1);
                }
                sL[(a0 * 7 + a1) * 16 + 8 + a2] = s0 + s1;
            }
        }
    }
    __syncthreads();

    if (tid < GG) {
        const float* row = sL + tid * 16;
        float m = row[0];
        #pragma unroll
        for (int i = 1; i < 7; i++)  m = fmaxf(m, row[i]);
        #pragma unroll
        for (int i = 8; i < 15; i++) m = fmaxf(m, row[i]);
        float e[16], sum = 0.f;
        #pragma unroll
        for (int i = 0; i < 7; i++)  { e[i] = __expf(row[i] - m); sum += e[i]; }
        #pragma unroll
        for (int i = 8; i < 15; i++) { e[i] = __expf(row[i] - m); sum += e[i]; }
        float inv = 1.f / sum;
        float4* dst = (float4*)&g_p[((size_t)n * GG + tid) * 16];
        dst[0] = make_float4(e[0] * inv,  e[1] * inv,  e[2] * inv,  e[3] * inv);
        dst[1] = make_float4(e[4] * inv,  e[5] * inv,  e[6] * inv,  0.f);
        dst[2] = make_float4(e[8] * inv,  e[9] * inv,  e[10] * inv, e[11] * inv);
        dst[3] = make_float4(e[12] * inv, e[13] * inv, e[14] * inv, 0.f);
    }
    __syncthreads();   // all g_p stores for this n issued
    // Allow PDL-dependent grid (kernel B) to launch; its griddepcontrol.wait
    // guarantees visibility of the stores above.
    asm volatile("griddepcontrol.launch_dependents;" ::: "memory");
}

// ---------------------------------------------------------------------------
// Kernel B (R8-proven): direct GMEM->reg V loads, p in smem, sOut transpose.
// grid = (N, Cv/128), block = 128, static smem 28.2KB -> 5 blocks/SM.
// Launched with PDL: vh LDGs (independent of A) issue BEFORE griddepcontrol.wait,
// overlapping A's tail; p is only read after the wait.
// ---------------------------------------------------------------------------
__global__ __launch_bounds__(128, 5) void ax_attn_out(
    const float* __restrict__ vH, const float* __restrict__ vW,
    float* __restrict__ out, int Cv)
{
    __shared__ float sOut[7 * 7 * 128];   // 6272
    __shared__ float sP[GG * 16];         // 784

    const int n   = blockIdx.x;
    const int c0  = blockIdx.y * 128;
    const int tid = threadIdx.x;
    const int c   = c0 + tid;
    const int ws  = Cv * 7;               // per-g stride in floats

    const float* bH = vH + (size_t)n * Cv * 49 + (size_t)c * 7;
    const float* bW = vW + (size_t)n * Cv * 49 + (size_t)c * 7;

    // direct GMEM->reg vH loads: 49 independent LDGs, issued before the PDL wait
    float vh[49];
    #pragma unroll
    for (int w = 0; w < 7; w++)
        #pragma unroll
        for (int j = 0; j < 7; j++)
            vh[w * 7 + j] = bH[w * ws + j];

    // wait for producer grid (A) — its g_p stores are visible after this
    asm volatile("griddepcontrol.wait;" ::: "memory");

    // stage p to smem
    {
        const float4* pg = (const float4*)&g_p[(size_t)n * GG * 16];
        float4 p0 = pg[tid];
        float4 p1; bool hp1 = (tid < 68);
        if (hp1) p1 = pg[tid + 128];
        ((float4*)sP)[tid] = p0;
        if (hp1) ((float4*)sP)[tid + 128] = p1;
    }
    __syncthreads();

    #pragma unroll
    for (int h = 0; h < 7; h++) {
        const float* bWh = bW + h * ws;
        float vw0 = bWh[0], vw1 = bWh[1], vw2 = bWh[2], vw3 = bWh[3];
        float vw4 = bWh[4], vw5 = bWh[5], vw6 = bWh[6];
        #pragma unroll
        for (int w = 0; w < 7; w++) {
            const float4* p4 = (const float4*)(sP + (h * 7 + w) * 16);
            float4 a = p4[0], b = p4[1], c4 = p4[2], d4 = p4[3];
            float s = a.x * vh[w * 7 + 0];
            s = fmaf(a.y, vh[w * 7 + 1], s);
            s = fmaf(a.z, vh[w * 7 + 2], s);
            s = fmaf(a.w, vh[w * 7 + 3], s);
            s = fmaf(b.x, vh[w * 7 + 4], s);
            s = fmaf(b.y, vh[w * 7 + 5], s);
            s = fmaf(b.z, vh[w * 7 + 6], s);
            s = fmaf(c4.x, vw0, s);
            s = fmaf(c4.y, vw1, s);
            s = fmaf(c4.z, vw2, s);
            s = fmaf(c4.w, vw3, s);
            s = fmaf(d4.x, vw4, s);
            s = fmaf(d4.y, vw5, s);
            s = fmaf(d4.z, vw6, s);
            sOut[tid * 49 + h * 7 + w] = s;   // stride 49 (coprime 32) -> conflict-free
        }
    }
    __syncthreads();

    // coalesced float4 write-out: sOut[c_local*49 + pos] == out[n, c0+c_local, pos]
    float* dst = out + ((size_t)n * Cv + c0) * GG;
    #pragma unroll
    for (int u = 0; u < 12; u++)
        ((float4*)dst)[tid + u * 128] = ((const float4*)sOut)[tid + u * 128];
    if (tid < 32)
        ((float4*)dst)[1536 + tid] = ((const float4*)sOut)[1536 + tid];
}

// ---------------------------------------------------------------------------
extern "C" void kernel_launch(void* const* d_in, const int* in_sizes, int n_in,
                              void* d_out, int out_size)
{
    const float* qH = (const float*)d_in[0];
    const float* kH = (const float*)d_in[1];
    const float* vH = (const float*)d_in[2];
    const float* qW = (const float*)d_in[3];
    const float* kW = (const float*)d_in[4];
    const float* vW = (const float*)d_in[5];

    const int B  = in_sizes[0] / (7 * CQ);    // 3584
    const int N  = B / 7;                     // 512
    const int Cv = in_sizes[2] / (B * 7);     // 512

    const size_t smemA = (size_t)14112 * sizeof(float);  // 56448
    cudaFuncSetAttribute(ax_attn_logits, cudaFuncAttributeMaxDynamicSharedMemorySize, (int)smemA);

    ax_attn_logits<<<N, 256, smemA>>>(qH, kH, qW, kW);

    // Kernel B with programmatic dependent launch: overlaps its V-load front
    // with A's tail; griddepcontrol.wait in B enforces the g_p dependency.
    cudaLaunchConfig_t cfg = {};
    cfg.gridDim  = dim3(N, Cv / 128);
    cfg.blockDim = dim3(128);
    cfg.dynamicSmemBytes = 0;
    cfg.stream = 0;
    cudaLaunchAttribute attrs[1];
    attrs[0].id = cudaLaunchAttributeProgrammaticStreamSerialization;
    attrs[0].val.programmaticStreamSerializationAllowed = 1;
    cfg.attrs = attrs;
    cfg.numAttrs = 1;
    cudaLaunchKernelEx(&cfg, ax_attn_out, vH, vW, (float*)d_out, Cv);
}